// round 12
// baseline (speedup 1.0000x reference)
#include <cuda_runtime.h>
#include <cuda_bf16.h>
#include <cstdint>

#define NN 100000
#define EE 1600000

typedef unsigned long long u64;

// Scratch (static device globals: allocation-free rule)
__device__ __align__(16) float g_agg1[NN * 128];   // pre-divided mean of x over in-neighbors
__device__ __align__(16) float g_hl[NN * 64];
__device__ __align__(16) float g_ho[NN * 64];
__device__ int g_deg[NN];
__device__ int g_off[NN + 1];
__device__ int g_cursor[NN];
__device__ int g_esrc[EE];     // edge srcs sorted by dst

__device__ __forceinline__ u64 fma2(u64 a, u64 b, u64 c) {
    u64 d; asm("fma.rn.f32x2 %0,%1,%2,%3;" : "=l"(d) : "l"(a), "l"(b), "l"(c));
    return d;
}
__device__ __forceinline__ u64 dup2(float v) {
    u64 r; asm("mov.b64 %0,{%1,%1};" : "=l"(r) : "f"(v)); return r;
}
__device__ __forceinline__ u64 pack2(float a, float b) {
    u64 r; asm("mov.b64 %0,{%1,%2};" : "=l"(r) : "f"(a), "f"(b)); return r;
}
__device__ __forceinline__ float2 unpack2(u64 v) {
    float2 f; asm("mov.b64 {%0,%1},%2;" : "=f"(f.x), "=f"(f.y) : "l"(v)); return f;
}

// ---------------------------------------------------------------------------
// CSR build: zero degree, histogram, scan, permute
// ---------------------------------------------------------------------------
__global__ void zero_deg_kernel() {
    int tid = blockIdx.x * blockDim.x + threadIdx.x;
    if (tid < NN) g_deg[tid] = 0;
}

__global__ void hist_kernel(const int* __restrict__ ei) {
    int tid = blockIdx.x * blockDim.x + threadIdx.x;
    int stride = gridDim.x * blockDim.x;
    for (int e = tid; e < EE; e += stride)
        atomicAdd(&g_deg[ei[EE + e]], 1);
}

// Single block, 1024 threads, 98 elements per thread
__global__ void scan_kernel() {
    __shared__ int part[1024];
    const int CH = 98;
    int t = threadIdx.x;
    int beg = t * CH;
    int end = min(beg + CH, NN);
    int s = 0;
    for (int i = beg; i < end; i++) s += g_deg[i];
    part[t] = s;
    __syncthreads();
    for (int o = 1; o < 1024; o <<= 1) {
        int v = (t >= o) ? part[t - o] : 0;
        __syncthreads();
        part[t] += v;
        __syncthreads();
    }
    int run = (t == 0) ? 0 : part[t - 1];
    for (int i = beg; i < end; i++) {
        g_off[i] = run;
        g_cursor[i] = run;
        run += g_deg[i];
    }
    if (t == 1023) g_off[NN] = run;   // == EE
}

__global__ void permute_kernel(const int* __restrict__ ei) {
    int tid = blockIdx.x * blockDim.x + threadIdx.x;
    int stride = gridDim.x * blockDim.x;
    for (int e = tid; e < EE; e += stride) {
        int s = ei[e];
        int d = ei[EE + e];
        int p = atomicAdd(&g_cursor[d], 1);
        g_esrc[p] = s;
    }
}

// ---------------------------------------------------------------------------
// Gather-aggregate layer 1: agg1[n] = mean_{s in N(n)} x[s]   (warp per node)
// 4-wide edge unroll for MLP.
// ---------------------------------------------------------------------------
__global__ void agg1_kernel(const float* __restrict__ x) {
    int w = (blockIdx.x * blockDim.x + threadIdx.x) >> 5;
    if (w >= NN) return;
    int lane = threadIdx.x & 31;
    int beg = g_off[w], end = g_off[w + 1];
    float4 a0 = make_float4(0.f, 0.f, 0.f, 0.f);
    float4 a1 = make_float4(0.f, 0.f, 0.f, 0.f);
    float4 a2 = make_float4(0.f, 0.f, 0.f, 0.f);
    float4 a3 = make_float4(0.f, 0.f, 0.f, 0.f);
    int j = beg;
    for (; j + 3 < end; j += 4) {
        int s0 = g_esrc[j],     s1 = g_esrc[j + 1];
        int s2 = g_esrc[j + 2], s3 = g_esrc[j + 3];
        float4 v0 = ((const float4*)(x + (size_t)s0 * 128))[lane];
        float4 v1 = ((const float4*)(x + (size_t)s1 * 128))[lane];
        float4 v2 = ((const float4*)(x + (size_t)s2 * 128))[lane];
        float4 v3 = ((const float4*)(x + (size_t)s3 * 128))[lane];
        a0.x += v0.x; a0.y += v0.y; a0.z += v0.z; a0.w += v0.w;
        a1.x += v1.x; a1.y += v1.y; a1.z += v1.z; a1.w += v1.w;
        a2.x += v2.x; a2.y += v2.y; a2.z += v2.z; a2.w += v2.w;
        a3.x += v3.x; a3.y += v3.y; a3.z += v3.z; a3.w += v3.w;
    }
    for (; j < end; j++) {
        int s0 = g_esrc[j];
        float4 v0 = ((const float4*)(x + (size_t)s0 * 128))[lane];
        a0.x += v0.x; a0.y += v0.y; a0.z += v0.z; a0.w += v0.w;
    }
    float inv = (end > beg) ? 1.0f / (float)(end - beg) : 0.f;
    float4 o;
    o.x = ((a0.x + a1.x) + (a2.x + a3.x)) * inv;
    o.y = ((a0.y + a1.y) + (a2.y + a3.y)) * inv;
    o.z = ((a0.z + a1.z) + (a2.z + a3.z)) * inv;
    o.w = ((a0.w + a1.w) + (a2.w + a3.w)) * inv;
    ((float4*)(g_agg1 + (size_t)w * 128))[lane] = o;
}

// ---------------------------------------------------------------------------
// Fused GEMM kernel (256 threads):
//   h  = relu(BN(mean1@W1l^T + b1l + x@W1r^T))        (smem only)
//   hl = h @ W2l^T -> g_hl ;  ho = h @ W2r^T + b2l -> g_ho
// ---------------------------------------------------------------------------
__global__ __launch_bounds__(256, 1)
void fused_kernel(const float* __restrict__ x,
                  const float* __restrict__ W1l,
                  const float* __restrict__ b1l,
                  const float* __restrict__ W1r,
                  const float* __restrict__ gamma,
                  const float* __restrict__ beta,
                  const float* __restrict__ rmean,
                  const float* __restrict__ rvar,
                  const float* __restrict__ W2l,
                  const float* __restrict__ b2l,
                  const float* __restrict__ W2r) {
    extern __shared__ float sm[];
    float* WTl = sm;             // 16384 floats
    float* WTr = sm + 16384;     // 16384
    float* W2c = sm + 32768;     // 16384
    float* buf = sm + 49152;     // 8 warps * 1024 floats

    for (int i = threadIdx.x; i < 16384; i += blockDim.x) {
        int k = i >> 7, j = i & 127;
        WTl[i] = W1l[j * 128 + k];
        WTr[i] = W1r[j * 128 + k];
        W2c[i] = (j < 64) ? W2l[j * 128 + k] : W2r[(j - 64) * 128 + k];
    }
    __syncthreads();

    int wid = threadIdx.x >> 5, lane = threadIdx.x & 31;
    float* mb = buf + wid * 1024;   // [4][128]  (mean, later h)
    float* xb = mb + 512;           // [4][128]  (x)

    float4 g4  = ((const float4*)gamma)[lane];
    float4 be4 = ((const float4*)beta)[lane];
    float4 rm4 = ((const float4*)rmean)[lane];
    float4 rv4 = ((const float4*)rvar)[lane];
    float4 bl4 = ((const float4*)b1l)[lane];
    float sx = g4.x * rsqrtf(rv4.x + 1e-5f);
    float sy = g4.y * rsqrtf(rv4.y + 1e-5f);
    float sz = g4.z * rsqrtf(rv4.z + 1e-5f);
    float sw = g4.w * rsqrtf(rv4.w + 1e-5f);
    u64 sc01 = pack2(sx, sy), sc23 = pack2(sz, sw);
    u64 sh01 = pack2((bl4.x - rm4.x) * sx + be4.x, (bl4.y - rm4.y) * sy + be4.y);
    u64 sh23 = pack2((bl4.z - rm4.z) * sz + be4.z, (bl4.w - rm4.w) * sw + be4.w);

    float4 b2v = make_float4(0.f, 0.f, 0.f, 0.f);
    if (lane >= 16) b2v = ((const float4*)b2l)[lane - 16];

    int gw = blockIdx.x * 8 + wid;
    int nw = gridDim.x * 8;
    const int NTASK = NN / 4;   // 25000

    for (int t = gw; t < NTASK; t += nw) {
        int base = t * 4;
        #pragma unroll
        for (int m = 0; m < 4; m++) {
            int node = base + m;
            ((float4*)(xb + m * 128))[lane] =
                ((const float4*)(x + (size_t)node * 128))[lane];
            ((float4*)(mb + m * 128))[lane] =
                ((const float4*)(g_agg1 + (size_t)node * 128))[lane];
        }
        __syncwarp();

        // ---- phase 1: acc = mean@W1l^T + x@W1r^T ----
        u64 acc0[4], acc1[4];
        #pragma unroll
        for (int m = 0; m < 4; m++) { acc0[m] = 0ull; acc1[m] = 0ull; }

        for (int k0 = 0; k0 < 128; k0 += 4) {
            float4 s[4];
            #pragma unroll
            for (int m = 0; m < 4; m++) s[m] = *(const float4*)(mb + m * 128 + k0);
            #pragma unroll
            for (int kk = 0; kk < 4; kk++) {
                ulonglong2 w = ((const ulonglong2*)(WTl + (k0 + kk) * 128))[lane];
                #pragma unroll
                for (int m = 0; m < 4; m++) {
                    float v = (kk == 0) ? s[m].x : (kk == 1) ? s[m].y
                             : (kk == 2) ? s[m].z : s[m].w;
                    u64 d = dup2(v);
                    acc0[m] = fma2(d, w.x, acc0[m]);
                    acc1[m] = fma2(d, w.y, acc1[m]);
                }
            }
            #pragma unroll
            for (int m = 0; m < 4; m++) s[m] = *(const float4*)(xb + m * 128 + k0);
            #pragma unroll
            for (int kk = 0; kk < 4; kk++) {
                ulonglong2 w = ((const ulonglong2*)(WTr + (k0 + kk) * 128))[lane];
                #pragma unroll
                for (int m = 0; m < 4; m++) {
                    float v = (kk == 0) ? s[m].x : (kk == 1) ? s[m].y
                             : (kk == 2) ? s[m].z : s[m].w;
                    u64 d = dup2(v);
                    acc0[m] = fma2(d, w.x, acc0[m]);
                    acc1[m] = fma2(d, w.y, acc1[m]);
                }
            }
        }

        // ---- epilogue 1: BN + ReLU -> h in mb ----
        __syncwarp();
        #pragma unroll
        for (int m = 0; m < 4; m++) {
            u64 h01 = fma2(acc0[m], sc01, sh01);
            u64 h23 = fma2(acc1[m], sc23, sh23);
            float2 a = unpack2(h01), b = unpack2(h23);
            float4 h4;
            h4.x = fmaxf(a.x, 0.f); h4.y = fmaxf(a.y, 0.f);
            h4.z = fmaxf(b.x, 0.f); h4.w = fmaxf(b.y, 0.f);
            ((float4*)(mb + m * 128))[lane] = h4;
        }
        __syncwarp();

        // ---- phase 2: [hl|ho] = h @ W2c ----
        u64 p0[4], p1[4];
        #pragma unroll
        for (int m = 0; m < 4; m++) { p0[m] = 0ull; p1[m] = 0ull; }

        for (int k0 = 0; k0 < 128; k0 += 4) {
            float4 s[4];
            #pragma unroll
            for (int m = 0; m < 4; m++) s[m] = *(const float4*)(mb + m * 128 + k0);
            #pragma unroll
            for (int kk = 0; kk < 4; kk++) {
                ulonglong2 w = ((const ulonglong2*)(W2c + (k0 + kk) * 128))[lane];
                #pragma unroll
                for (int m = 0; m < 4; m++) {
                    float v = (kk == 0) ? s[m].x : (kk == 1) ? s[m].y
                             : (kk == 2) ? s[m].z : s[m].w;
                    u64 d = dup2(v);
                    p0[m] = fma2(d, w.x, p0[m]);
                    p1[m] = fma2(d, w.y, p1[m]);
                }
            }
        }

        #pragma unroll
        for (int m = 0; m < 4; m++) {
            float2 a = unpack2(p0[m]), b = unpack2(p1[m]);
            int node = base + m;
            if (lane < 16) {
                float4 v = make_float4(a.x, a.y, b.x, b.y);
                ((float4*)(g_hl + (size_t)node * 64))[lane] = v;
            } else {
                float4 v = make_float4(a.x + b2v.x, a.y + b2v.y,
                                       b.x + b2v.z, b.y + b2v.w);
                ((float4*)(g_ho + (size_t)node * 64))[lane - 16] = v;
            }
        }
        __syncwarp();
    }
}

// ---------------------------------------------------------------------------
// Gather-aggregate layer 2 + output:
//   out[n] = ho[n] + mean_{s in N(n)} hl[s]
// 4-wide edge unroll for MLP; warp per node, float2/lane.
// ---------------------------------------------------------------------------
__global__ void agg2_out_kernel(float* __restrict__ out) {
    int w = (blockIdx.x * blockDim.x + threadIdx.x) >> 5;
    if (w >= NN) return;
    int lane = threadIdx.x & 31;
    int beg = g_off[w], end = g_off[w + 1];
    float2 a0 = make_float2(0.f, 0.f);
    float2 a1 = make_float2(0.f, 0.f);
    float2 a2 = make_float2(0.f, 0.f);
    float2 a3 = make_float2(0.f, 0.f);
    int j = beg;
    for (; j + 3 < end; j += 4) {
        int s0 = g_esrc[j],     s1 = g_esrc[j + 1];
        int s2 = g_esrc[j + 2], s3 = g_esrc[j + 3];
        float2 v0 = ((const float2*)(g_hl + (size_t)s0 * 64))[lane];
        float2 v1 = ((const float2*)(g_hl + (size_t)s1 * 64))[lane];
        float2 v2 = ((const float2*)(g_hl + (size_t)s2 * 64))[lane];
        float2 v3 = ((const float2*)(g_hl + (size_t)s3 * 64))[lane];
        a0.x += v0.x; a0.y += v0.y;
        a1.x += v1.x; a1.y += v1.y;
        a2.x += v2.x; a2.y += v2.y;
        a3.x += v3.x; a3.y += v3.y;
    }
    for (; j < end; j++) {
        int s0 = g_esrc[j];
        float2 v0 = ((const float2*)(g_hl + (size_t)s0 * 64))[lane];
        a0.x += v0.x; a0.y += v0.y;
    }
    float inv = (end > beg) ? 1.0f / (float)(end - beg) : 0.f;
    float2 ho = ((const float2*)(g_ho + (size_t)w * 64))[lane];
    float2 o;
    o.x = ho.x + ((a0.x + a1.x) + (a2.x + a3.x)) * inv;
    o.y = ho.y + ((a0.y + a1.y) + (a2.y + a3.y)) * inv;
    ((float2*)(out + (size_t)w * 64))[lane] = o;
}

// ---------------------------------------------------------------------------
extern "C" void kernel_launch(void* const* d_in, const int* in_sizes, int n_in,
                              void* d_out, int out_size) {
    const float* x     = (const float*)d_in[0];
    const int*   ei    = (const int*)d_in[1];
    const float* W1l   = (const float*)d_in[2];
    const float* b1l   = (const float*)d_in[3];
    const float* W1r   = (const float*)d_in[4];
    const float* gamma = (const float*)d_in[5];
    const float* beta  = (const float*)d_in[6];
    const float* rmean = (const float*)d_in[7];
    const float* rvar  = (const float*)d_in[8];
    const float* W2l   = (const float*)d_in[9];
    const float* b2l   = (const float*)d_in[10];
    const float* W2r   = (const float*)d_in[11];
    float* out = (float*)d_out;

    const int SMEMF = (49152 + 8 * 1024) * 4;   // 229376 B
    cudaFuncSetAttribute(fused_kernel, cudaFuncAttributeMaxDynamicSharedMemorySize, SMEMF);

    zero_deg_kernel<<<(NN + 255) / 256, 256>>>();
    hist_kernel<<<2048, 256>>>(ei);
    scan_kernel<<<1, 1024>>>();
    permute_kernel<<<2048, 256>>>(ei);
    agg1_kernel<<<12500, 256>>>(x);
    fused_kernel<<<152, 256, SMEMF>>>(x, W1l, b1l, W1r, gamma, beta, rmean,
                                      rvar, W2l, b2l, W2r);
    agg2_out_kernel<<<12500, 256>>>(out);
}